// round 14
// baseline (speedup 1.0000x reference)
#include <cuda_runtime.h>
#include <cuda_fp16.h>

typedef unsigned long long ull;

// Problem constants (fixed by the dataset)
#define BB 32
#define NN 200
#define DD 100
#define IT 16             // i-rows per block (two 8-row groups)
#define C14 14            // 8-half d-chunks per row (112 padded, score K)
#define DPAD 104          // padded d rows in htd
#define JPAD 208          // padded j cols in htd / pp (13 k16 tiles)
#define PTS 17            // pt row stride (floats): odd -> conflict-free column reads
#define PPS 216           // pp row stride (halves)
#define NEGV (-9e15f)

// smem (floats): gf(fp16) | pt(f32) | pp(fp16)
#define OFF_PT  3584                         // gf: 4*7*32*8 halves = 3584 floats
#define OFF_PP  (OFF_PT + NN*PTS)            // pt: 3400 floats
#define SMEM_FLOATS (OFF_PP + (16*PPS)/2)    // pp: 3456 halves = 1728 floats
#define SMEM_BYTES  (SMEM_FLOATS*4)          // 34848 B

// fp16 transposed gathered embeddings: ht[b][c14][j][8 halves]
__device__ __half ht_scratch[(size_t)BB * C14 * NN * 8];
// fp16 edge weights: ah[c14][k][8 halves]
__device__ __half ah_scratch[C14 * 4 * 8];
// fp16 d-major embeddings for agg B-fragments: htd[b][d][j]
__device__ __half htd_scratch[(size_t)BB * DPAD * JPAD];

// ---- fused prep: gather emb -> ht (j-major chunks) + htd (d-major) + ah ----
__global__ __launch_bounds__(256)
void prep_kernel(const int* __restrict__ inputs,
                 const float* __restrict__ emb,
                 const float* __restrict__ a0,
                 const float* __restrict__ a1,
                 const float* __restrict__ a2,
                 const float* __restrict__ a3)
{
    __shared__ __half th[112][26];   // [d][r], r = j within this block's group
    const int jg   = blockIdx.x;
    const int b    = blockIdx.y;
    const int tid  = threadIdx.x;
    const int w    = tid >> 5;
    const int lane = tid & 31;

    if (jg == 8) {
        for (int u = tid; u < DPAD * 8; u += 256) {
            int d = u >> 3, jj = NN + (u & 7);
            htd_scratch[((size_t)b * DPAD + d) * JPAD + jj] = __float2half(0.f);
        }
        return;
    }

    for (int u = tid; u < (112 * 26) / 2; u += 256)
        ((unsigned*)th)[u] = 0u;
    __syncthreads();

    const int j0 = jg * 25;
    for (int r = w; r < 25; r += 8) {
        int j = j0 + r;
        int id = inputs[b * NN + j];
        if (lane < 25) {
            float4 v = *(const float4*)(emb + (size_t)id * DD + 4 * lane);
            __half h4[4];
            h4[0] = __float2half(v.x); h4[1] = __float2half(v.y);
            h4[2] = __float2half(v.z); h4[3] = __float2half(v.w);
            *(ull*)(ht_scratch + (((size_t)b * C14 + (lane >> 1)) * NN + j) * 8
                    + (lane & 1) * 4) = *(ull*)h4;
            int d = 4 * lane;
            th[d][r] = h4[0]; th[d + 1][r] = h4[1];
            th[d + 2][r] = h4[2]; th[d + 3][r] = h4[3];
        } else if (lane < 28) {
            int c   = (lane == 25) ? 12 : 13;
            int off = (lane == 26) ? 0 : 4;
            *(ull*)(ht_scratch + (((size_t)b * C14 + c) * NN + j) * 8 + off) = 0ull;
        }
    }
    __syncthreads();

    for (int d = w; d < DPAD; d += 8) {
        if (lane < 25)
            htd_scratch[((size_t)b * DPAD + d) * JPAD + j0 + lane] = th[d][lane];
    }

    if (jg == 0 && b == 0 && tid < 4) {
        const float* ak = (tid == 0) ? a0 : (tid == 1) ? a1 : (tid == 2) ? a2 : a3;
        for (int c = 0; c < C14; ++c) {
            __half h[8];
#pragma unroll
            for (int r = 0; r < 8; ++r) {
                int d = c * 8 + r;
                h[r] = __float2half(d < DD ? ak[d] : 0.f);
            }
            *(uint4*)(ah_scratch + (c * 4 + tid) * 8) = *(uint4*)h;
        }
    }
}

__global__ __launch_bounds__(256, 3)
void gnn_agg_kernel(const int* __restrict__ adj,
                    float* __restrict__ out)
{
    extern __shared__ float sm[];
    __half* gf = (__half*)sm;             // A frags: [(t4id*7+ks)*32+lane][8 halves]
    float*  pt = sm + OFF_PT;             // [NN][PTS] (first 16 used): alpha staging
    __half* pp = (__half*)(sm + OFF_PP);  // [16][PPS]: fp16 softmax weights
    __shared__ int2 kb_s[NN];             // nibbles: .x rows 0-7, .y rows 8-15

    const int b    = blockIdx.y;
    const int i0   = blockIdx.x * IT;
    const int tid  = threadIdx.x;
    const int w    = tid >> 5;
    const int lane = tid & 31;
    const int gid  = lane >> 2;      // 0..7
    const int tig  = lane & 3;       // 0..3

    // ---- kb table: 16 i-rows per j ----
    if (tid < NN) {
        unsigned lo = 0, hi = 0;
        const int* ap = adj + ((size_t)b * NN + i0) * NN + tid;
#pragma unroll
        for (int i = 0; i < IT; ++i) {
            int a = (i0 + i < NN) ? ap[(size_t)i * NN] : 0;
            unsigned valid = (a >= 1 && a <= 4) ? 4u : 0u;
            unsigned ksel = valid ? (unsigned)(a - 1) : 0u;
            unsigned nib = (ksel | valid);
            if (i < 8) lo |= nib << (4 * i);
            else       hi |= nib << (4 * (i - 8));
        }
        kb_s[tid] = make_int2((int)lo, (int)hi);
    }

    // ---- pt pre-init to NEG; pp pre-init to 0 ----
    for (int u = tid; u < NN * 16; u += 256) {
        int jj = u >> 4, ii = u & 15;
        pt[jj * PTS + ii] = NEGV;
    }
    for (int u = tid; u < (16 * PPS) / 2; u += 256)
        ((unsigned*)pp)[u] = 0u;

    // ---- stage A fragments for score: 4 tiles (mt = k-pair, ig = i-group) ----
    for (int e = tid; e < 896; e += 256) {
        int t4id = e / 224, rem = e - t4id * 224;
        int ks = rem >> 5, l = rem & 31;
        int g8 = l >> 2, t4 = l & 3;
        int mt = t4id >> 1, ig = t4id & 1;
        int i = i0 + ig * 8 + g8;
        if (i >= NN) i = NN - 1;          // clamp (junk masked by kb)
        int cp = t4 * 2;
        int c8a = 2 * ks, c8b = 2 * ks + 1;
        __half2 hlo = *(const __half2*)(ht_scratch + (((size_t)b * C14 + c8a) * NN + i) * 8 + cp);
        __half2 hhi = *(const __half2*)(ht_scratch + (((size_t)b * C14 + c8b) * NN + i) * 8 + cp);
        int ka = 2 * mt, kb2 = 2 * mt + 1;
        __half2 alo_a = *(const __half2*)(ah_scratch + (c8a * 4 + ka)  * 8 + cp);
        __half2 alo_b = *(const __half2*)(ah_scratch + (c8a * 4 + kb2) * 8 + cp);
        __half2 ahi_a = *(const __half2*)(ah_scratch + (c8b * 4 + ka)  * 8 + cp);
        __half2 ahi_b = *(const __half2*)(ah_scratch + (c8b * 4 + kb2) * 8 + cp);
        __half2 pk[4];
        pk[0] = __hmul2(hlo, alo_a);
        pk[1] = __hmul2(hlo, alo_b);
        pk[2] = __hmul2(hhi, ahi_a);
        pk[3] = __hmul2(hhi, ahi_b);
        *(uint4*)(gf + (size_t)(t4id * 7 + ks) * 32 * 8 + l * 8) = *(uint4*)pk;
    }
    __syncthreads();

    // ---- score via HMMA: warp owns tile t4id = w&3, nt stride 2 ----
    const int t4id = w & 3;
    const int mt = t4id >> 1;
    const int ig = t4id & 1;
    unsigned aF[7][4];
#pragma unroll
    for (int ks = 0; ks < 7; ++ks)
        *(uint4*)aF[ks] = *(const uint4*)(gf + (size_t)(t4id * 7 + ks) * 32 * 8 + lane * 8);

    const __half* htb = ht_scratch + (size_t)b * C14 * NN * 8;
    for (int nt = (w >> 2); nt < 25; nt += 2) {
        int jB = nt * 8 + gid;
        unsigned b0[7], b1[7];
#pragma unroll
        for (int ks = 0; ks < 7; ++ks) {
            b0[ks] = *(const unsigned*)(htb + ((size_t)(2 * ks)     * NN + jB) * 8 + tig * 2);
            b1[ks] = *(const unsigned*)(htb + ((size_t)(2 * ks + 1) * NN + jB) * 8 + tig * 2);
        }
        float cA0 = 0.f, cA1 = 0.f, cA2 = 0.f, cA3 = 0.f;
        float cB0 = 0.f, cB1 = 0.f, cB2 = 0.f, cB3 = 0.f;
#pragma unroll
        for (int ks = 0; ks < 7; ks += 2) {
            asm("mma.sync.aligned.m16n8k16.row.col.f32.f16.f16.f32 "
                "{%0,%1,%2,%3}, {%4,%5,%6,%7}, {%8,%9}, {%0,%1,%2,%3};"
                : "+f"(cA0), "+f"(cA1), "+f"(cA2), "+f"(cA3)
                : "r"(aF[ks][0]), "r"(aF[ks][1]), "r"(aF[ks][2]), "r"(aF[ks][3]),
                  "r"(b0[ks]), "r"(b1[ks]));
        }
#pragma unroll
        for (int ks = 1; ks < 7; ks += 2) {
            asm("mma.sync.aligned.m16n8k16.row.col.f32.f16.f16.f32 "
                "{%0,%1,%2,%3}, {%4,%5,%6,%7}, {%8,%9}, {%0,%1,%2,%3};"
                : "+f"(cB0), "+f"(cB1), "+f"(cB2), "+f"(cB3)
                : "r"(aF[ks][0]), "r"(aF[ks][1]), "r"(aF[ks][2]), "r"(aF[ks][3]),
                  "r"(b0[ks]), "r"(b1[ks]));
        }
        float c0 = cA0 + cB0, c1 = cA1 + cB1;
        float c2 = cA2 + cB2, c3 = cA3 + cB3;
        int j0 = nt * 8 + tig * 2;
        int2 kv0 = kb_s[j0];
        int2 kv1 = kb_s[j0 + 1];
        unsigned k0 = (unsigned)(ig ? kv0.y : kv0.x) >> (4 * gid);
        unsigned k1 = (unsigned)(ig ? kv1.y : kv1.x) >> (4 * gid);
        unsigned ka = (unsigned)(2 * mt), kbv = ka + 1;
        int iloc = ig * 8 + gid;
        if ((k0 & 4u) && (k0 & 3u) == ka)  pt[j0 * PTS + iloc]       = (c0 >= 0.f) ? c0 : 0.2f * c0;
        if ((k1 & 4u) && (k1 & 3u) == ka)  pt[(j0 + 1) * PTS + iloc] = (c1 >= 0.f) ? c1 : 0.2f * c1;
        if ((k0 & 4u) && (k0 & 3u) == kbv) pt[j0 * PTS + iloc]       = (c2 >= 0.f) ? c2 : 0.2f * c2;
        if ((k1 & 4u) && (k1 & 3u) == kbv) pt[(j0 + 1) * PTS + iloc] = (c3 >= 0.f) ? c3 : 0.2f * c3;
    }
    __syncthreads();

    // ---- softmax: warp w owns rows 2w and 2w+1 ----
#pragma unroll
    for (int r = 0; r < 2; ++r) {
        int irow = 2 * w + r;
        float al[7];
#pragma unroll
        for (int t = 0; t < 7; ++t) {
            int jj = lane + 32 * t;
            al[t] = (jj < NN) ? pt[jj * PTS + irow] : NEGV;
        }
        float m = al[0];
#pragma unroll
        for (int t = 1; t < 7; ++t) m = fmaxf(m, al[t]);
#pragma unroll
        for (int off = 16; off > 0; off >>= 1)
            m = fmaxf(m, __shfl_xor_sync(0xffffffffu, m, off));

        float pv[7];
        float sum = 0.f;
#pragma unroll
        for (int t = 0; t < 7; ++t) {
            int jj = lane + 32 * t;
            float e = (jj < NN) ? __expf(al[t] - m) : 0.f;
            pv[t] = e;
            sum += e;
        }
#pragma unroll
        for (int off = 16; off > 0; off >>= 1)
            sum += __shfl_xor_sync(0xffffffffu, sum, off);
        float rinv = 1.f / sum;
#pragma unroll
        for (int t = 0; t < 7; ++t) {
            int jj = lane + 32 * t;
            if (jj < NN) pp[irow * PPS + jj] = __float2half(pv[t] * rinv);
        }
    }
    __syncthreads();

    // ---- aggregation via HMMA: warps 0-3 -> i-group 0, warps 4-7 -> i-group 1 ----
    {
        const int aig = w >> 2;              // i-group 0/1
        const int nt0 = w & 3;               // nt start, stride 4
        unsigned pA0[13], pA1[13];
#pragma unroll
        for (int kt = 0; kt < 13; ++kt) {
            pA0[kt] = *(const unsigned*)(pp + (aig * 8 + gid) * PPS + kt * 16 + tig * 2);
            pA1[kt] = *(const unsigned*)(pp + (aig * 8 + gid) * PPS + kt * 16 + tig * 2 + 8);
        }

        for (int nt = nt0; nt < 13; nt += 4) {
            const __half* hb = htd_scratch + ((size_t)b * DPAD + nt * 8 + gid) * JPAD + tig * 2;
            unsigned hb0[13], hb1[13];
#pragma unroll
            for (int kt = 0; kt < 13; ++kt) {
                hb0[kt] = *(const unsigned*)(hb + kt * 16);
                hb1[kt] = *(const unsigned*)(hb + kt * 16 + 8);
            }
            float cA0 = 0.f, cA1 = 0.f, cA2 = 0.f, cA3 = 0.f;
            float cB0 = 0.f, cB1 = 0.f, cB2 = 0.f, cB3 = 0.f;
#pragma unroll
            for (int kt = 0; kt < 13; kt += 2) {
                asm("mma.sync.aligned.m16n8k16.row.col.f32.f16.f16.f32 "
                    "{%0,%1,%2,%3}, {%4,%5,%6,%7}, {%8,%9}, {%0,%1,%2,%3};"
                    : "+f"(cA0), "+f"(cA1), "+f"(cA2), "+f"(cA3)
                    : "r"(pA0[kt]), "r"(0u), "r"(pA1[kt]), "r"(0u),
                      "r"(hb0[kt]), "r"(hb1[kt]));
            }
#pragma unroll
            for (int kt = 1; kt < 13; kt += 2) {
                asm("mma.sync.aligned.m16n8k16.row.col.f32.f16.f16.f32 "
                    "{%0,%1,%2,%3}, {%4,%5,%6,%7}, {%8,%9}, {%0,%1,%2,%3};"
                    : "+f"(cB0), "+f"(cB1), "+f"(cB2), "+f"(cB3)
                    : "r"(pA0[kt]), "r"(0u), "r"(pA1[kt]), "r"(0u),
                      "r"(hb0[kt]), "r"(hb1[kt]));
            }
            int d0 = nt * 8 + tig * 2;
            int orow = i0 + aig * 8 + gid;
            if (d0 < DD && orow < NN) {
                float2 o;
                o.x = cA0 + cB0;
                o.y = cA1 + cB1;
                *(float2*)(out + (size_t)(b * NN + orow) * DD + d0) = o;
            }
        }
    }
}

extern "C" void kernel_launch(void* const* d_in, const int* in_sizes, int n_in,
                              void* d_out, int out_size)
{
    const int*   inputs = (const int*)d_in[0];
    const int*   adj    = (const int*)d_in[1];
    // d_in[2] = mask_item (unused by reference)
    const float* emb    = (const float*)d_in[3];
    const float* a0     = (const float*)d_in[4];
    const float* a1     = (const float*)d_in[5];
    const float* a2     = (const float*)d_in[6];
    const float* a3     = (const float*)d_in[7];
    float*       out    = (float*)d_out;

    cudaFuncSetAttribute(gnn_agg_kernel,
                         cudaFuncAttributeMaxDynamicSharedMemorySize,
                         SMEM_BYTES);

    // Phase 1: fused gather + fp16 transposes (ht, htd, ah)
    dim3 pg(9, BB);      // 9 x 32 = 288 blocks
    prep_kernel<<<pg, 256>>>(inputs, emb, a0, a1, a2, a3);

    // Phase 2: fused HMMA-score / softmax / HMMA-aggregate
    dim3 grid((NN + IT - 1) / IT, BB);   // 13 x 32 = 416 blocks (~1 wave at 3/SM)
    gnn_agg_kernel<<<grid, 256, SMEM_BYTES>>>(adj, out);
}